// round 9
// baseline (speedup 1.0000x reference)
#include <cuda_runtime.h>
#include <cuda_bf16.h>
#include <cstdint>

#define NROWS 8192
#define NCODES 8192
#define HID 256
#define EPS 0.5f
#define CAP 320

typedef unsigned long long u64;

// ---------------------------------------------------------------------------
// Device scratch (static globals — allocation-free)
// ---------------------------------------------------------------------------
__device__ __align__(16) __nv_bfloat16 g_hbf[NROWS * HID];
__device__ __align__(16) __nv_bfloat16 g_cbf[NCODES * HID];
__device__ float g_hsq[NROWS];
__device__ float g_csq[NCODES];
__device__ __align__(16) u64 g_cand[(size_t)NROWS * CAP];   // ~21 MB
__device__ int g_ccount[NROWS];

__device__ __forceinline__ uint32_t smem_u32(const void* p) {
    uint32_t a;
    asm("{ .reg .u64 t; cvta.to.shared.u64 t, %1; cvt.u32.u64 %0, t; }"
        : "=r"(a) : "l"(p));
    return a;
}
__device__ __forceinline__ void cp16(uint32_t dst, const void* src) {
    asm volatile("cp.async.cg.shared.global [%0], [%1], 16;" :: "r"(dst), "l"(src));
}
#define CP_COMMIT() asm volatile("cp.async.commit_group;" ::: "memory")
#define CP_WAIT0()  asm volatile("cp.async.wait_group 0;"  ::: "memory")
#define CP_WAIT1()  asm volatile("cp.async.wait_group 1;"  ::: "memory")

#define LDSM_X4(r0, r1, r2, r3, addr)                                          \
    asm volatile("ldmatrix.sync.aligned.m8n8.x4.shared.b16 {%0,%1,%2,%3}, [%4];" \
                 : "=r"(r0), "=r"(r1), "=r"(r2), "=r"(r3) : "r"(addr))

#define MMA16816(d, a0, a1, a2, a3, b0, b1)                                    \
    asm volatile(                                                              \
        "mma.sync.aligned.m16n8k16.row.col.f32.bf16.bf16.f32 "                 \
        "{%0,%1,%2,%3}, {%4,%5,%6,%7}, {%8,%9}, {%0,%1,%2,%3};"                \
        : "+f"((d)[0]), "+f"((d)[1]), "+f"((d)[2]), "+f"((d)[3])               \
        : "r"(a0), "r"(a1), "r"(a2), "r"(a3), "r"(b0), "r"(b1))

// order-preserving float<->uint map
__device__ __forceinline__ unsigned enc_f(float f) {
    unsigned u = __float_as_uint(f);
    return (u & 0x80000000u) ? ~u : (u | 0x80000000u);
}
__device__ __forceinline__ float dec_f(unsigned e) {
    unsigned u = (e & 0x80000000u) ? (e ^ 0x80000000u) : ~e;
    return __uint_as_float(u);
}

// ---------------------------------------------------------------------------
// Fused fp32->bf16 convert + squared norms (one warp per row) + counter reset
// ---------------------------------------------------------------------------
__global__ void convert_norms_kernel(const float* __restrict__ h,
                                     const float* __restrict__ cb) {
    if (blockIdx.x < NROWS / 256)
        g_ccount[blockIdx.x * 256 + threadIdx.x] = 0;

    int warp = (blockIdx.x * blockDim.x + threadIdx.x) >> 5;
    int lane = threadIdx.x & 31;
    const float* src;
    __nv_bfloat16* dst;
    float* nrm;
    if (warp < NROWS) {
        src = h + (size_t)warp * HID; dst = g_hbf + (size_t)warp * HID; nrm = &g_hsq[warp];
    } else {
        int r = warp - NROWS;
        if (r >= NCODES) return;
        src = cb + (size_t)r * HID; dst = g_cbf + (size_t)r * HID; nrm = &g_csq[r];
    }
    float s = 0.f;
#pragma unroll
    for (int half2i = 0; half2i < 2; ++half2i) {
        float4 a = ((const float4*)src)[lane + half2i * 32];
        s = fmaf(a.x, a.x, s); s = fmaf(a.y, a.y, s);
        s = fmaf(a.z, a.z, s); s = fmaf(a.w, a.w, s);
        __nv_bfloat162 p0 = __floats2bfloat162_rn(a.x, a.y);
        __nv_bfloat162 p1 = __floats2bfloat162_rn(a.z, a.w);
        uint2 w;
        w.x = *reinterpret_cast<uint32_t*>(&p0);
        w.y = *reinterpret_cast<uint32_t*>(&p1);
        ((uint2*)dst)[lane + half2i * 32] = w;
    }
#pragma unroll
    for (int o = 16; o; o >>= 1) s += __shfl_xor_sync(0xFFFFFFFFu, s, o);
    if (lane == 0) *nrm = s;
}

// ---------------------------------------------------------------------------
// bf16 HMMA GEMM: one 128x128 tile per CTA (4096 CTAs).
// K=256 split into 2 stages of 128, cp.async double-buffered (load||compute).
// Fused epilogue: per-row block min -> candidate push. No bulk stores.
// ---------------------------------------------------------------------------
#define STG_STRIDE 272               // 256B data + 16B pad (conflict-free)
#define STG_BYTES (128 * STG_STRIDE) // 34816 per matrix per stage
#define SM_TOTAL (4 * STG_BYTES + 512)

__global__ __launch_bounds__(256, 1) void vq_gemm_kernel() {
    extern __shared__ char smem[];
    const uint32_t sb = smem_u32(smem);
    const int tid = threadIdx.x;
    const int lane = tid & 31;
    const int wid = tid >> 5;
    const int wm = wid & 1;          // warp row (2 x 64)
    const int wn = wid >> 1;         // warp col (4 x 32)
    const int row0 = blockIdx.y * 128;
    const int col0 = blockIdx.x * 128;
    unsigned* rowmin = (unsigned*)(smem + 4 * STG_BYTES);

    // smem stage bases: A0, B0, A1, B1
    const uint32_t smA[2] = {sb, sb + 2 * STG_BYTES};
    const uint32_t smB[2] = {sb + STG_BYTES, sb + 3 * STG_BYTES};

    const char* asrc = (const char*)(g_hbf + (size_t)row0 * HID);
    const char* bsrc = (const char*)(g_cbf + (size_t)col0 * HID);

    // Prefetch both K-stages (each: 128 rows x 256B of A and B)
#pragma unroll
    for (int s = 0; s < 2; ++s) {
#pragma unroll
        for (int i = 0; i < 8; ++i) {
            int idx = tid + i * 256;
            int r = idx >> 4, c = idx & 15;            // 16 x 16B chunks per row
            cp16(smA[s] + r * STG_STRIDE + c * 16, asrc + r * 512 + s * 256 + c * 16);
            cp16(smB[s] + r * STG_STRIDE + c * 16, bsrc + r * 512 + s * 256 + c * 16);
        }
        CP_COMMIT();
    }
    if (tid < 128) rowmin[tid] = 0xFFFFFFFFu;

    float acc[4][4][4];              // [mi][ni][reg]
#pragma unroll
    for (int mi = 0; mi < 4; ++mi)
#pragma unroll
        for (int ni = 0; ni < 4; ++ni)
#pragma unroll
            for (int q = 0; q < 4; ++q) acc[mi][ni][q] = 0.f;

    const int lrow = lane & 15;
    const int lkc  = lane >> 4;

    // --- Stage loop: compute stage 0 while stage 1 still loads ---
#pragma unroll
    for (int s = 0; s < 2; ++s) {
        if (s == 0) CP_WAIT1(); else CP_WAIT0();
        __syncthreads();

        const uint32_t aAddr0 = smA[s] + (wm * 64 + lrow) * STG_STRIDE + lkc * 16;
        const uint32_t bAddr0 = smB[s] + (wn * 32 + lrow) * STG_STRIDE + lkc * 16;
#pragma unroll
        for (int ks = 0; ks < 8; ++ks) {
            const uint32_t koff = (uint32_t)ks * 32;
            uint32_t a[4][4], b[2][4];
#pragma unroll
            for (int mi = 0; mi < 4; ++mi)
                LDSM_X4(a[mi][0], a[mi][1], a[mi][2], a[mi][3],
                        aAddr0 + mi * 16 * STG_STRIDE + koff);
#pragma unroll
            for (int nj = 0; nj < 2; ++nj)
                LDSM_X4(b[nj][0], b[nj][1], b[nj][2], b[nj][3],
                        bAddr0 + nj * 16 * STG_STRIDE + koff);
#pragma unroll
            for (int mi = 0; mi < 4; ++mi) {
#pragma unroll
                for (int nj = 0; nj < 2; ++nj) {
                    MMA16816(acc[mi][2 * nj],     a[mi][0], a[mi][1], a[mi][2], a[mi][3],
                             b[nj][0], b[nj][2]);
                    MMA16816(acc[mi][2 * nj + 1], a[mi][0], a[mi][1], a[mi][2], a[mi][3],
                             b[nj][1], b[nj][3]);
                }
            }
        }
    }

    // --- Epilogue: score = csq - 2*dot (in place) ---
    float2 csq2[4];
#pragma unroll
    for (int ni = 0; ni < 4; ++ni)
        csq2[ni] = *(const float2*)&g_csq[col0 + wn * 32 + ni * 8 + 2 * (lane & 3)];
#pragma unroll
    for (int mi = 0; mi < 4; ++mi)
#pragma unroll
        for (int ni = 0; ni < 4; ++ni) {
            acc[mi][ni][0] = csq2[ni].x - 2.0f * acc[mi][ni][0];
            acc[mi][ni][1] = csq2[ni].y - 2.0f * acc[mi][ni][1];
            acc[mi][ni][2] = csq2[ni].x - 2.0f * acc[mi][ni][2];
            acc[mi][ni][3] = csq2[ni].y - 2.0f * acc[mi][ni][3];
        }

    // per-row min across warp's 32 cols (quad shuffle) -> smem atomicMin
#pragma unroll
    for (int mi = 0; mi < 4; ++mi)
#pragma unroll
        for (int hh = 0; hh < 2; ++hh) {
            float m = acc[mi][0][2 * hh];
#pragma unroll
            for (int ni = 0; ni < 4; ++ni) {
                m = fminf(m, acc[mi][ni][2 * hh]);
                m = fminf(m, acc[mi][ni][2 * hh + 1]);
            }
            m = fminf(m, __shfl_xor_sync(0xFFFFFFFFu, m, 1));
            m = fminf(m, __shfl_xor_sync(0xFFFFFFFFu, m, 2));
            if ((lane & 3) == 0)
                atomicMin(&rowmin[wm * 64 + mi * 16 + (lane >> 2) + hh * 8], enc_f(m));
        }
    __syncthreads();

    // push candidates within EPS of block-local row min
#pragma unroll
    for (int mi = 0; mi < 4; ++mi)
#pragma unroll
        for (int hh = 0; hh < 2; ++hh) {
            const int rloc = wm * 64 + mi * 16 + (lane >> 2) + hh * 8;
            const float thr = dec_f(rowmin[rloc]) + EPS;
            const int grow = row0 + rloc;
#pragma unroll
            for (int ni = 0; ni < 4; ++ni)
#pragma unroll
                for (int q2 = 0; q2 < 2; ++q2) {
                    float v = acc[mi][ni][2 * hh + q2];
                    if (v < thr) {
                        int col = col0 + wn * 32 + ni * 8 + 2 * (lane & 3) + q2;
                        int p = atomicAdd(&g_ccount[grow], 1);
                        if (p < CAP)
                            g_cand[(size_t)grow * CAP + p] =
                                ((u64)enc_f(v) << 32) | (unsigned)col;
                    }
                }
        }
}

// ---------------------------------------------------------------------------
// Select + output write: 1 warp per row. Candidate scan -> exact fp32 rescore
// -> stream the full one-hot row (zeros with 1.0 substituted) + loss.
// ---------------------------------------------------------------------------
__global__ __launch_bounds__(256) void select_kernel(const float* __restrict__ h,
                                                     const float* __restrict__ cbp,
                                                     float* __restrict__ out) {
    const int row = blockIdx.x * 8 + (threadIdx.x >> 5);
    const int lane = threadIdx.x & 31;
    const unsigned FULL = 0xFFFFFFFFu;

    const int n = min(g_ccount[row], CAP);
    const u64* lst = &g_cand[(size_t)row * CAP];

    u64 bmin = 0xFFFFFFFFFFFFFFFFull;
    for (int i = lane; i < n; i += 32) bmin = min(bmin, lst[i]);
#pragma unroll
    for (int o = 16; o; o >>= 1) {
        u64 t = __shfl_xor_sync(FULL, bmin, o);
        if (t < bmin) bmin = t;
    }
    const float thr = dec_f((unsigned)(bmin >> 32)) + EPS;
    const float hsq = g_hsq[row];
    const float4* hp = (const float4*)(h + (size_t)row * HID);
    const float4 ha = hp[lane * 2];
    const float4 hb = hp[lane * 2 + 1];

    u64 bestkey = 0xFFFFFFFFFFFFFFFFull;
    for (int base = 0; base < n; base += 32) {
        int i = base + lane;
        u64 e = (i < n) ? lst[i] : 0xFFFFFFFFFFFFFFFFull;
        bool ok = (i < n) && (dec_f((unsigned)(e >> 32)) < thr);
        unsigned mask = __ballot_sync(FULL, ok);
        while (mask) {
            int j = __ffs(mask) - 1;
            mask &= mask - 1;
            unsigned col = __shfl_sync(FULL, (unsigned)(e & 0xFFFFFFFFull), j);
            const float4* cp = (const float4*)(cbp + (size_t)col * HID);
            float4 ca = cp[lane * 2];
            float4 cbv = cp[lane * 2 + 1];
            float d = 0.f;
            d = fmaf(ha.x, ca.x, d);  d = fmaf(ha.y, ca.y, d);
            d = fmaf(ha.z, ca.z, d);  d = fmaf(ha.w, ca.w, d);
            d = fmaf(hb.x, cbv.x, d); d = fmaf(hb.y, cbv.y, d);
            d = fmaf(hb.z, cbv.z, d); d = fmaf(hb.w, cbv.w, d);
#pragma unroll
            for (int o = 16; o; o >>= 1) d += __shfl_xor_sync(FULL, d, o);
            float s = __fadd_rn(__fsub_rn(hsq, __fmul_rn(2.0f, d)), g_csq[col]);
            u64 key = ((u64)enc_f(s) << 32) | col;
            if (key < bestkey) bestkey = key;
        }
    }

    const unsigned idx = (unsigned)(bestkey & 0xFFFFFFFFull);

    // --- Stream the one-hot row: 2048 x 16B chunks per row (8192 floats) ---
    uint4* orow = (uint4*)(out + (size_t)row * NCODES);
    const int hot_chunk = idx >> 2;
    const int hot_sub = idx & 3;
#pragma unroll 8
    for (int it = 0; it < 64; ++it) {
        int c16 = it * 32 + lane;
        uint4 v = make_uint4(0, 0, 0, 0);
        if (c16 == hot_chunk) (&v.x)[hot_sub] = 0x3F800000u;  // 1.0f
        orow[c16] = v;
    }

    // --- Loss: exact mean((h - z_q)^2) * 1.25 ---
    const float4* cp = (const float4*)(cbp + (size_t)idx * HID);
    float4 ca = cp[lane * 2];
    float4 cbv = cp[lane * 2 + 1];
    float s = 0.f;
    float d;
    d = ha.x - ca.x;  s = fmaf(d, d, s);  d = ha.y - ca.y;  s = fmaf(d, d, s);
    d = ha.z - ca.z;  s = fmaf(d, d, s);  d = ha.w - ca.w;  s = fmaf(d, d, s);
    d = hb.x - cbv.x; s = fmaf(d, d, s);  d = hb.y - cbv.y; s = fmaf(d, d, s);
    d = hb.z - cbv.z; s = fmaf(d, d, s);  d = hb.w - cbv.w; s = fmaf(d, d, s);
#pragma unroll
    for (int o = 16; o; o >>= 1) s += __shfl_xor_sync(FULL, s, o);

    if (lane == 0) {
        float m = s * (1.0f / (float)HID);
        out[(size_t)NROWS * NCODES + row] = __fadd_rn(m, __fmul_rn(0.25f, m));
    }
}

// ---------------------------------------------------------------------------
extern "C" void kernel_launch(void* const* d_in, const int* in_sizes, int n_in,
                              void* d_out, int out_size) {
    const float* h  = (const float*)d_in[0];   // (8192, 256)
    const float* cb = (const float*)d_in[2];   // (8192, 256)
    float* out = (float*)d_out;

    static bool attr_set = false;
    if (!attr_set) {
        cudaFuncSetAttribute(vq_gemm_kernel,
                             cudaFuncAttributeMaxDynamicSharedMemorySize, SM_TOTAL);
        attr_set = true;
    }

    convert_norms_kernel<<<(NROWS + NCODES) / 8, 256>>>(h, cb);

    dim3 grid(NCODES / 128, NROWS / 128);  // (64, 64)
    vq_gemm_kernel<<<grid, 256, SM_TOTAL>>>();

    select_kernel<<<NROWS / 8, 256>>>(h, cb, out);
}

// round 10
// speedup vs baseline: 1.0738x; 1.0738x over previous
#include <cuda_runtime.h>
#include <cuda_bf16.h>
#include <cstdint>

#define NROWS 8192
#define NCODES 8192
#define HID 256
#define EPS 0.5f
#define CAP 512

typedef unsigned long long u64;

// ---------------------------------------------------------------------------
// Device scratch (static globals — allocation-free)
// ---------------------------------------------------------------------------
__device__ __align__(16) __nv_bfloat16 g_hbf[NROWS * HID];
__device__ __align__(16) __nv_bfloat16 g_cbf[NCODES * HID];
__device__ float g_hsq[NROWS];
__device__ float g_csq[NCODES];
__device__ __align__(16) u64 g_cand[(size_t)NROWS * CAP];   // 32 MB
__device__ int g_ccount[NROWS];

__device__ __forceinline__ uint32_t smem_u32(const void* p) {
    uint32_t a;
    asm("{ .reg .u64 t; cvta.to.shared.u64 t, %1; cvt.u32.u64 %0, t; }"
        : "=r"(a) : "l"(p));
    return a;
}
__device__ __forceinline__ void cp16(uint32_t dst, const void* src) {
    asm volatile("cp.async.cg.shared.global [%0], [%1], 16;" :: "r"(dst), "l"(src));
}
#define CP_COMMIT() asm volatile("cp.async.commit_group;" ::: "memory")
#define CP_WAIT0()  asm volatile("cp.async.wait_group 0;"  ::: "memory")
#define CP_WAIT1()  asm volatile("cp.async.wait_group 1;"  ::: "memory")

#define LDSM_X4(r0, r1, r2, r3, addr)                                          \
    asm volatile("ldmatrix.sync.aligned.m8n8.x4.shared.b16 {%0,%1,%2,%3}, [%4];" \
                 : "=r"(r0), "=r"(r1), "=r"(r2), "=r"(r3) : "r"(addr))

#define MMA16816(d, a0, a1, a2, a3, b0, b1)                                    \
    asm volatile(                                                              \
        "mma.sync.aligned.m16n8k16.row.col.f32.bf16.bf16.f32 "                 \
        "{%0,%1,%2,%3}, {%4,%5,%6,%7}, {%8,%9}, {%0,%1,%2,%3};"                \
        : "+f"((d)[0]), "+f"((d)[1]), "+f"((d)[2]), "+f"((d)[3])               \
        : "r"(a0), "r"(a1), "r"(a2), "r"(a3), "r"(b0), "r"(b1))

// order-preserving float<->uint map
__device__ __forceinline__ unsigned enc_f(float f) {
    unsigned u = __float_as_uint(f);
    return (u & 0x80000000u) ? ~u : (u | 0x80000000u);
}
__device__ __forceinline__ float dec_f(unsigned e) {
    unsigned u = (e & 0x80000000u) ? (e ^ 0x80000000u) : ~e;
    return __uint_as_float(u);
}

// ---------------------------------------------------------------------------
// Fused fp32->bf16 convert + squared norms (one warp per row) + counter reset
// ---------------------------------------------------------------------------
__global__ void convert_norms_kernel(const float* __restrict__ h,
                                     const float* __restrict__ cb) {
    if (blockIdx.x < NROWS / 256)
        g_ccount[blockIdx.x * 256 + threadIdx.x] = 0;

    int warp = (blockIdx.x * blockDim.x + threadIdx.x) >> 5;
    int lane = threadIdx.x & 31;
    const float* src;
    __nv_bfloat16* dst;
    float* nrm;
    if (warp < NROWS) {
        src = h + (size_t)warp * HID; dst = g_hbf + (size_t)warp * HID; nrm = &g_hsq[warp];
    } else {
        int r = warp - NROWS;
        if (r >= NCODES) return;
        src = cb + (size_t)r * HID; dst = g_cbf + (size_t)r * HID; nrm = &g_csq[r];
    }
    float s = 0.f;
#pragma unroll
    for (int half2i = 0; half2i < 2; ++half2i) {
        float4 a = ((const float4*)src)[lane + half2i * 32];
        s = fmaf(a.x, a.x, s); s = fmaf(a.y, a.y, s);
        s = fmaf(a.z, a.z, s); s = fmaf(a.w, a.w, s);
        __nv_bfloat162 p0 = __floats2bfloat162_rn(a.x, a.y);
        __nv_bfloat162 p1 = __floats2bfloat162_rn(a.z, a.w);
        uint2 w;
        w.x = *reinterpret_cast<uint32_t*>(&p0);
        w.y = *reinterpret_cast<uint32_t*>(&p1);
        ((uint2*)dst)[lane + half2i * 32] = w;
    }
#pragma unroll
    for (int o = 16; o; o >>= 1) s += __shfl_xor_sync(0xFFFFFFFFu, s, o);
    if (lane == 0) *nrm = s;
}

// ---------------------------------------------------------------------------
// bf16 HMMA GEMM: 128x128 tile per CTA, OCCUPANCY 2 (two CTAs overlap).
// K chunked 4x64, double-buffered cp.async. Epilogue: warp-local row-min
// candidate filter, no smem, no block sync. No bulk stores.
// ---------------------------------------------------------------------------
#define CH_STRIDE 144                    // 128B data + 16B pad, conflict-free
#define CH_MAT   (128 * CH_STRIDE)       // 18432 per matrix per chunk
#define CH_BUF   (2 * CH_MAT)            // A+B per chunk
#define SM_TOTAL (2 * CH_BUF)            // 73728 -> 2 CTAs/SM fit in 228KB

__global__ __launch_bounds__(256, 2) void vq_gemm_kernel() {
    extern __shared__ char smem[];
    const uint32_t sb = smem_u32(smem);
    const int tid = threadIdx.x;
    const int lane = tid & 31;
    const int wid = tid >> 5;
    const int wm = wid & 1;          // warp row (2 x 64)
    const int wn = wid >> 1;         // warp col (4 x 32)
    const int row0 = blockIdx.y * 128;
    const int col0 = blockIdx.x * 128;

    const char* asrc = (const char*)(g_hbf + (size_t)row0 * HID);
    const char* bsrc = (const char*)(g_cbf + (size_t)col0 * HID);

    // chunk loader: 128 rows x 128B per matrix -> 4 cp16 per thread per matrix
    const int lr = tid >> 3;            // 0..31 base row (4 strided sets of 32)
    const int lc = tid & 7;             // 16B column within 128B
    auto load_chunk = [&](int ck, int buf) {
        const uint32_t bA = sb + buf * CH_BUF;
        const uint32_t bB = bA + CH_MAT;
        const int goff = ck * 128 + lc * 16;
#pragma unroll
        for (int i = 0; i < 4; ++i) {
            int r = lr + i * 32;
            cp16(bA + r * CH_STRIDE + lc * 16, asrc + r * 512 + goff);
            cp16(bB + r * CH_STRIDE + lc * 16, bsrc + r * 512 + goff);
        }
    };

    load_chunk(0, 0); CP_COMMIT();
    load_chunk(1, 1); CP_COMMIT();

    float acc[4][4][4];
#pragma unroll
    for (int mi = 0; mi < 4; ++mi)
#pragma unroll
        for (int ni = 0; ni < 4; ++ni)
#pragma unroll
            for (int q = 0; q < 4; ++q) acc[mi][ni][q] = 0.f;

    const int lrow = lane & 15;
    const int lkc  = lane >> 4;

#pragma unroll
    for (int ck = 0; ck < 4; ++ck) {
        if (ck < 3) CP_WAIT1(); else CP_WAIT0();
        __syncthreads();

        const uint32_t bufb = sb + (ck & 1) * CH_BUF;
        const uint32_t aAddr0 = bufb + (wm * 64 + lrow) * CH_STRIDE + lkc * 16;
        const uint32_t bAddr0 = bufb + CH_MAT + (wn * 32 + lrow) * CH_STRIDE + lkc * 16;
#pragma unroll
        for (int ks = 0; ks < 4; ++ks) {
            const uint32_t koff = (uint32_t)ks * 32;
            uint32_t a[4][4], b[2][4];
#pragma unroll
            for (int mi = 0; mi < 4; ++mi)
                LDSM_X4(a[mi][0], a[mi][1], a[mi][2], a[mi][3],
                        aAddr0 + mi * 16 * CH_STRIDE + koff);
#pragma unroll
            for (int nj = 0; nj < 2; ++nj)
                LDSM_X4(b[nj][0], b[nj][1], b[nj][2], b[nj][3],
                        bAddr0 + nj * 16 * CH_STRIDE + koff);
#pragma unroll
            for (int mi = 0; mi < 4; ++mi) {
#pragma unroll
                for (int nj = 0; nj < 2; ++nj) {
                    MMA16816(acc[mi][2 * nj],     a[mi][0], a[mi][1], a[mi][2], a[mi][3],
                             b[nj][0], b[nj][2]);
                    MMA16816(acc[mi][2 * nj + 1], a[mi][0], a[mi][1], a[mi][2], a[mi][3],
                             b[nj][1], b[nj][3]);
                }
            }
        }

        if (ck < 2) {
            __syncthreads();             // all warps done reading buf ck&1
            load_chunk(ck + 2, ck & 1);
            CP_COMMIT();
        }
    }

    // --- Epilogue (register-only): score = csq - 2*dot; warp-local row min;
    //     push all elements within EPS of the warp-chunk min.
    float2 csq2[4];
#pragma unroll
    for (int ni = 0; ni < 4; ++ni)
        csq2[ni] = *(const float2*)&g_csq[col0 + wn * 32 + ni * 8 + 2 * (lane & 3)];
#pragma unroll
    for (int mi = 0; mi < 4; ++mi)
#pragma unroll
        for (int ni = 0; ni < 4; ++ni) {
            acc[mi][ni][0] = csq2[ni].x - 2.0f * acc[mi][ni][0];
            acc[mi][ni][1] = csq2[ni].y - 2.0f * acc[mi][ni][1];
            acc[mi][ni][2] = csq2[ni].x - 2.0f * acc[mi][ni][2];
            acc[mi][ni][3] = csq2[ni].y - 2.0f * acc[mi][ni][3];
        }

#pragma unroll
    for (int mi = 0; mi < 4; ++mi)
#pragma unroll
        for (int hh = 0; hh < 2; ++hh) {
            float m = acc[mi][0][2 * hh];
#pragma unroll
            for (int ni = 0; ni < 4; ++ni) {
                m = fminf(m, acc[mi][ni][2 * hh]);
                m = fminf(m, acc[mi][ni][2 * hh + 1]);
            }
            m = fminf(m, __shfl_xor_sync(0xFFFFFFFFu, m, 1));
            m = fminf(m, __shfl_xor_sync(0xFFFFFFFFu, m, 2));
            const float thr = m + EPS;
            const int grow = row0 + wm * 64 + mi * 16 + (lane >> 2) + hh * 8;
#pragma unroll
            for (int ni = 0; ni < 4; ++ni)
#pragma unroll
                for (int q2 = 0; q2 < 2; ++q2) {
                    float v = acc[mi][ni][2 * hh + q2];
                    if (v < thr) {
                        int col = col0 + wn * 32 + ni * 8 + 2 * (lane & 3) + q2;
                        int p = atomicAdd(&g_ccount[grow], 1);
                        if (p < CAP)
                            g_cand[(size_t)grow * CAP + p] =
                                ((u64)enc_f(v) << 32) | (unsigned)col;
                    }
                }
        }
}

// ---------------------------------------------------------------------------
// Select + output write: 1 warp per row. Candidate scan -> exact fp32 rescore
// -> stream full one-hot row + loss. No dynamic indexing (no local spill).
// ---------------------------------------------------------------------------
__global__ __launch_bounds__(256) void select_kernel(const float* __restrict__ h,
                                                     const float* __restrict__ cbp,
                                                     float* __restrict__ out) {
    const int row = blockIdx.x * 8 + (threadIdx.x >> 5);
    const int lane = threadIdx.x & 31;
    const unsigned FULL = 0xFFFFFFFFu;

    const int n = min(g_ccount[row], CAP);
    const u64* lst = &g_cand[(size_t)row * CAP];

    u64 bmin = 0xFFFFFFFFFFFFFFFFull;
    for (int i = lane; i < n; i += 32) bmin = min(bmin, lst[i]);
#pragma unroll
    for (int o = 16; o; o >>= 1) {
        u64 t = __shfl_xor_sync(FULL, bmin, o);
        if (t < bmin) bmin = t;
    }
    const float thr = dec_f((unsigned)(bmin >> 32)) + EPS;
    const float hsq = g_hsq[row];
    const float4* hp = (const float4*)(h + (size_t)row * HID);
    const float4 ha = hp[lane * 2];
    const float4 hb = hp[lane * 2 + 1];

    u64 bestkey = 0xFFFFFFFFFFFFFFFFull;
    for (int base = 0; base < n; base += 32) {
        int i = base + lane;
        u64 e = (i < n) ? lst[i] : 0xFFFFFFFFFFFFFFFFull;
        bool ok = (i < n) && (dec_f((unsigned)(e >> 32)) < thr);
        unsigned mask = __ballot_sync(FULL, ok);
        while (mask) {
            int j = __ffs(mask) - 1;
            mask &= mask - 1;
            unsigned col = __shfl_sync(FULL, (unsigned)(e & 0xFFFFFFFFull), j);
            const float4* cp = (const float4*)(cbp + (size_t)col * HID);
            float4 ca = cp[lane * 2];
            float4 cbv = cp[lane * 2 + 1];
            float d = 0.f;
            d = fmaf(ha.x, ca.x, d);  d = fmaf(ha.y, ca.y, d);
            d = fmaf(ha.z, ca.z, d);  d = fmaf(ha.w, ca.w, d);
            d = fmaf(hb.x, cbv.x, d); d = fmaf(hb.y, cbv.y, d);
            d = fmaf(hb.z, cbv.z, d); d = fmaf(hb.w, cbv.w, d);
#pragma unroll
            for (int o = 16; o; o >>= 1) d += __shfl_xor_sync(FULL, d, o);
            float s = __fadd_rn(__fsub_rn(hsq, __fmul_rn(2.0f, d)), g_csq[col]);
            u64 key = ((u64)enc_f(s) << 32) | col;
            if (key < bestkey) bestkey = key;
        }
    }

    const unsigned idx = (unsigned)(bestkey & 0xFFFFFFFFull);

    // --- Stream one-hot row: 2048 x 16B chunks (8192 floats), no dyn-index ---
    uint4* orow = (uint4*)(out + (size_t)row * NCODES);
    const int hot_chunk = idx >> 2;
    const int hot_sub = idx & 3;
    const unsigned h0 = (hot_sub == 0) ? 0x3F800000u : 0u;
    const unsigned h1 = (hot_sub == 1) ? 0x3F800000u : 0u;
    const unsigned h2 = (hot_sub == 2) ? 0x3F800000u : 0u;
    const unsigned h3 = (hot_sub == 3) ? 0x3F800000u : 0u;
#pragma unroll 8
    for (int it = 0; it < 64; ++it) {
        int c16 = it * 32 + lane;
        uint4 v = make_uint4(0, 0, 0, 0);
        if (c16 == hot_chunk) { v.x = h0; v.y = h1; v.z = h2; v.w = h3; }
        orow[c16] = v;
    }

    // --- Loss: exact mean((h - z_q)^2) * 1.25 ---
    const float4* cp = (const float4*)(cbp + (size_t)idx * HID);
    float4 ca = cp[lane * 2];
    float4 cbv = cp[lane * 2 + 1];
    float s = 0.f;
    float d;
    d = ha.x - ca.x;  s = fmaf(d, d, s);  d = ha.y - ca.y;  s = fmaf(d, d, s);
    d = ha.z - ca.z;  s = fmaf(d, d, s);  d = ha.w - ca.w;  s = fmaf(d, d, s);
    d = hb.x - cbv.x; s = fmaf(d, d, s);  d = hb.y - cbv.y; s = fmaf(d, d, s);
    d = hb.z - cbv.z; s = fmaf(d, d, s);  d = hb.w - cbv.w; s = fmaf(d, d, s);
#pragma unroll
    for (int o = 16; o; o >>= 1) s += __shfl_xor_sync(FULL, s, o);

    if (lane == 0) {
        float m = s * (1.0f / (float)HID);
        out[(size_t)NROWS * NCODES + row] = __fadd_rn(m, __fmul_rn(0.25f, m));
    }
}

// ---------------------------------------------------------------------------
extern "C" void kernel_launch(void* const* d_in, const int* in_sizes, int n_in,
                              void* d_out, int out_size) {
    const float* h  = (const float*)d_in[0];   // (8192, 256)
    const float* cb = (const float*)d_in[2];   // (8192, 256)
    float* out = (float*)d_out;

    static bool attr_set = false;
    if (!attr_set) {
        cudaFuncSetAttribute(vq_gemm_kernel,
                             cudaFuncAttributeMaxDynamicSharedMemorySize, SM_TOTAL);
        attr_set = true;
    }

    convert_norms_kernel<<<(NROWS + NCODES) / 8, 256>>>(h, cb);

    dim3 grid(NCODES / 128, NROWS / 128);  // (64, 64)
    vq_gemm_kernel<<<grid, 256, SM_TOTAL>>>();

    select_kernel<<<NROWS / 8, 256>>>(h, cb, out);
}

// round 11
// speedup vs baseline: 2.1109x; 1.9658x over previous
#include <cuda_runtime.h>
#include <cuda_bf16.h>
#include <cstdint>

#define NROWS 8192
#define NCODES 8192
#define HID 256
#define EPS 1.0f
#define MAXC 256

typedef unsigned long long u64;

// ---------------------------------------------------------------------------
// Device scratch (static globals — allocation-free)
// ---------------------------------------------------------------------------
__device__ __align__(16) __nv_bfloat16 g_hbf[NROWS * HID];
__device__ __align__(16) __nv_bfloat16 g_cbf[NCODES * HID];
__device__ float g_hsq[NROWS];
__device__ float g_csq[NCODES];
__device__ __align__(16) __nv_bfloat16 g_score[(size_t)NROWS * NCODES];  // 128 MB

__device__ __forceinline__ uint32_t smem_u32(const void* p) {
    uint32_t a;
    asm("{ .reg .u64 t; cvta.to.shared.u64 t, %1; cvt.u32.u64 %0, t; }"
        : "=r"(a) : "l"(p));
    return a;
}
__device__ __forceinline__ void cp16(uint32_t dst, const void* src) {
    asm volatile("cp.async.cg.shared.global [%0], [%1], 16;" :: "r"(dst), "l"(src));
}
#define CP_COMMIT() asm volatile("cp.async.commit_group;" ::: "memory")
#define CP_WAIT0()  asm volatile("cp.async.wait_group 0;"  ::: "memory")
#define CP_WAIT1()  asm volatile("cp.async.wait_group 1;"  ::: "memory")

#define LDSM_X4(r0, r1, r2, r3, addr)                                          \
    asm volatile("ldmatrix.sync.aligned.m8n8.x4.shared.b16 {%0,%1,%2,%3}, [%4];" \
                 : "=r"(r0), "=r"(r1), "=r"(r2), "=r"(r3) : "r"(addr))

#define MMA16816(d, a0, a1, a2, a3, b0, b1)                                    \
    asm volatile(                                                              \
        "mma.sync.aligned.m16n8k16.row.col.f32.bf16.bf16.f32 "                 \
        "{%0,%1,%2,%3}, {%4,%5,%6,%7}, {%8,%9}, {%0,%1,%2,%3};"                \
        : "+f"((d)[0]), "+f"((d)[1]), "+f"((d)[2]), "+f"((d)[3])               \
        : "r"(a0), "r"(a1), "r"(a2), "r"(a3), "r"(b0), "r"(b1))

// order-preserving float<->uint map
__device__ __forceinline__ unsigned enc_f(float f) {
    unsigned u = __float_as_uint(f);
    return (u & 0x80000000u) ? ~u : (u | 0x80000000u);
}

// ---------------------------------------------------------------------------
// Fused fp32->bf16 convert + squared norms (one warp per row)
// ---------------------------------------------------------------------------
__global__ void convert_norms_kernel(const float* __restrict__ h,
                                     const float* __restrict__ cb) {
    int warp = (blockIdx.x * blockDim.x + threadIdx.x) >> 5;
    int lane = threadIdx.x & 31;
    const float* src;
    __nv_bfloat16* dst;
    float* nrm;
    if (warp < NROWS) {
        src = h + (size_t)warp * HID; dst = g_hbf + (size_t)warp * HID; nrm = &g_hsq[warp];
    } else {
        int r = warp - NROWS;
        if (r >= NCODES) return;
        src = cb + (size_t)r * HID; dst = g_cbf + (size_t)r * HID; nrm = &g_csq[r];
    }
    float s = 0.f;
#pragma unroll
    for (int half2i = 0; half2i < 2; ++half2i) {
        float4 a = ((const float4*)src)[lane + half2i * 32];
        s = fmaf(a.x, a.x, s); s = fmaf(a.y, a.y, s);
        s = fmaf(a.z, a.z, s); s = fmaf(a.w, a.w, s);
        __nv_bfloat162 p0 = __floats2bfloat162_rn(a.x, a.y);
        __nv_bfloat162 p1 = __floats2bfloat162_rn(a.z, a.w);
        uint2 w;
        w.x = *reinterpret_cast<uint32_t*>(&p0);
        w.y = *reinterpret_cast<uint32_t*>(&p1);
        ((uint2*)dst)[lane + half2i * 32] = w;
    }
#pragma unroll
    for (int o = 16; o; o >>= 1) s += __shfl_xor_sync(0xFFFFFFFFu, s, o);
    if (lane == 0) *nrm = s;
}

// ---------------------------------------------------------------------------
// bf16 HMMA GEMM: 128x128 tile per CTA (4096 CTAs), OCCUPANCY 2.
// K chunked 4x64, double-buffered cp.async (cross-CTA + intra overlap).
// Epilogue: bf16 score staging in smem -> coalesced 256B-row writes.
// NO atomics, NO candidate lists.
// ---------------------------------------------------------------------------
#define CH_STRIDE 144                    // 128B data + 16B pad, conflict-free
#define CH_MAT   (128 * CH_STRIDE)       // 18432 per matrix per chunk
#define CH_BUF   (2 * CH_MAT)            // A+B per chunk
#define SM_TOTAL (2 * CH_BUF)            // 73728 -> 2 CTAs/SM
#define SC_STRIDE 272                    // score staging row stride (bytes)

__global__ __launch_bounds__(256, 2) void vq_gemm_kernel() {
    extern __shared__ char smem[];
    const uint32_t sb = smem_u32(smem);
    const int tid = threadIdx.x;
    const int lane = tid & 31;
    const int wid = tid >> 5;
    const int wm = wid & 1;          // warp row (2 x 64)
    const int wn = wid >> 1;         // warp col (4 x 32)
    const int row0 = blockIdx.y * 128;
    const int col0 = blockIdx.x * 128;

    const char* asrc = (const char*)(g_hbf + (size_t)row0 * HID);
    const char* bsrc = (const char*)(g_cbf + (size_t)col0 * HID);

    // chunk loader: 128 rows x 128B per matrix -> 4 cp16 per thread per matrix
    const int lr = tid >> 3;            // 0..31 base row
    const int lc = tid & 7;             // 16B column within 128B
    auto load_chunk = [&](int ck, int buf) {
        const uint32_t bA = sb + buf * CH_BUF;
        const uint32_t bB = bA + CH_MAT;
        const int goff = ck * 128 + lc * 16;
#pragma unroll
        for (int i = 0; i < 4; ++i) {
            int r = lr + i * 32;
            cp16(bA + r * CH_STRIDE + lc * 16, asrc + r * 512 + goff);
            cp16(bB + r * CH_STRIDE + lc * 16, bsrc + r * 512 + goff);
        }
    };

    load_chunk(0, 0); CP_COMMIT();
    load_chunk(1, 1); CP_COMMIT();

    float acc[4][4][4];
#pragma unroll
    for (int mi = 0; mi < 4; ++mi)
#pragma unroll
        for (int ni = 0; ni < 4; ++ni)
#pragma unroll
            for (int q = 0; q < 4; ++q) acc[mi][ni][q] = 0.f;

    const int lrow = lane & 15;
    const int lkc  = lane >> 4;

#pragma unroll
    for (int ck = 0; ck < 4; ++ck) {
        if (ck < 3) CP_WAIT1(); else CP_WAIT0();
        __syncthreads();

        const uint32_t bufb = sb + (ck & 1) * CH_BUF;
        const uint32_t aAddr0 = bufb + (wm * 64 + lrow) * CH_STRIDE + lkc * 16;
        const uint32_t bAddr0 = bufb + CH_MAT + (wn * 32 + lrow) * CH_STRIDE + lkc * 16;
#pragma unroll
        for (int ks = 0; ks < 4; ++ks) {
            const uint32_t koff = (uint32_t)ks * 32;
            uint32_t a[4][4], b[2][4];
#pragma unroll
            for (int mi = 0; mi < 4; ++mi)
                LDSM_X4(a[mi][0], a[mi][1], a[mi][2], a[mi][3],
                        aAddr0 + mi * 16 * CH_STRIDE + koff);
#pragma unroll
            for (int nj = 0; nj < 2; ++nj)
                LDSM_X4(b[nj][0], b[nj][1], b[nj][2], b[nj][3],
                        bAddr0 + nj * 16 * CH_STRIDE + koff);
#pragma unroll
            for (int mi = 0; mi < 4; ++mi) {
#pragma unroll
                for (int nj = 0; nj < 2; ++nj) {
                    MMA16816(acc[mi][2 * nj],     a[mi][0], a[mi][1], a[mi][2], a[mi][3],
                             b[nj][0], b[nj][2]);
                    MMA16816(acc[mi][2 * nj + 1], a[mi][0], a[mi][1], a[mi][2], a[mi][3],
                             b[nj][1], b[nj][3]);
                }
            }
        }

        if (ck < 2) {
            __syncthreads();             // all warps done reading buf ck&1
            load_chunk(ck + 2, ck & 1);
            CP_COMMIT();
        }
    }
    __syncthreads();  // done with chunk buffers — reuse as score staging

    // --- Epilogue: score = csq - 2*dot, pack bf16x2, stage in smem ---
    float2 csq2[4];
#pragma unroll
    for (int ni = 0; ni < 4; ++ni)
        csq2[ni] = *(const float2*)&g_csq[col0 + wn * 32 + ni * 8 + 2 * (lane & 3)];

    const int erow = wm * 64 + (lane >> 2);
    const int ecol = wn * 32 + 2 * (lane & 3);
#pragma unroll
    for (int mi = 0; mi < 4; ++mi) {
#pragma unroll
        for (int ni = 0; ni < 4; ++ni) {
            float s0 = csq2[ni].x - 2.0f * acc[mi][ni][0];
            float s1 = csq2[ni].y - 2.0f * acc[mi][ni][1];
            float s2 = csq2[ni].x - 2.0f * acc[mi][ni][2];
            float s3 = csq2[ni].y - 2.0f * acc[mi][ni][3];
            __nv_bfloat162 p01 = __floats2bfloat162_rn(s0, s1);
            __nv_bfloat162 p23 = __floats2bfloat162_rn(s2, s3);
            int r = erow + mi * 16;
            int cbyte = (ecol + ni * 8) * 2;
            *(uint32_t*)(smem + r * SC_STRIDE + cbyte) =
                *reinterpret_cast<uint32_t*>(&p01);
            *(uint32_t*)(smem + (r + 8) * SC_STRIDE + cbyte) =
                *reinterpret_cast<uint32_t*>(&p23);
        }
    }
    __syncthreads();

    // --- Coalesced copy-out: 128 rows x 256B ---
#pragma unroll
    for (int i = 0; i < 8; ++i) {
        int idx = tid + i * 256;
        int r = idx >> 4, q = idx & 15;
        uint4 v = *(const uint4*)(smem + r * SC_STRIDE + q * 16);
        *(uint4*)(g_score + (size_t)(row0 + r) * NCODES + col0 + q * 8) = v;
    }
}

// ---------------------------------------------------------------------------
// Select + output: one block (256 threads) per row. Scan bf16 scores,
// candidates within EPS of min, exact fp32 rescore (reference rounding),
// stream one-hot row (fused zeroing) + loss.
// ---------------------------------------------------------------------------
__global__ __launch_bounds__(256) void select_kernel(const float* __restrict__ h,
                                                     const float* __restrict__ cbp,
                                                     float* __restrict__ out) {
    const int row = blockIdx.x;
    const int tid = threadIdx.x;
    const int wid = tid >> 5;
    const int lane = tid & 31;

    __shared__ float sh[HID];
    __shared__ float wmin[8];
    __shared__ float sthr;
    __shared__ int scand[MAXC];
    __shared__ int scnt;
    __shared__ unsigned long long skey;
    __shared__ unsigned sidx;

    if (tid == 0) { scnt = 0; skey = 0xFFFFFFFFFFFFFFFFull; }
    sh[tid] = h[(size_t)row * HID + tid];

    const uint4* srow = (const uint4*)(g_score + (size_t)row * NCODES);
    uint4 v[4];
    float lmin = 3.4e38f;
#pragma unroll
    for (int i = 0; i < 4; ++i) {
        v[i] = srow[tid + i * 256];
        const uint32_t* u = &v[i].x;
#pragma unroll
        for (int q = 0; q < 4; ++q) {
            float2 f = __bfloat1622float2(*reinterpret_cast<const __nv_bfloat162*>(&u[q]));
            lmin = fminf(lmin, fminf(f.x, f.y));
        }
    }
#pragma unroll
    for (int o = 16; o; o >>= 1) lmin = fminf(lmin, __shfl_xor_sync(0xFFFFFFFFu, lmin, o));
    if (lane == 0) wmin[wid] = lmin;
    __syncthreads();
    if (tid == 0) {
        float m = wmin[0];
#pragma unroll
        for (int i = 1; i < 8; ++i) m = fminf(m, wmin[i]);
        sthr = m + EPS;
    }
    __syncthreads();
    const float thr = sthr;

    // collect candidates
#pragma unroll
    for (int i = 0; i < 4; ++i) {
        const uint32_t* u = &v[i].x;
        int cbase = (tid + i * 256) * 8;
#pragma unroll
        for (int q = 0; q < 4; ++q) {
            float2 f = __bfloat1622float2(*reinterpret_cast<const __nv_bfloat162*>(&u[q]));
            if (f.x < thr) { int p = atomicAdd(&scnt, 1); if (p < MAXC) scand[p] = cbase + 2 * q; }
            if (f.y < thr) { int p = atomicAdd(&scnt, 1); if (p < MAXC) scand[p] = cbase + 2 * q + 1; }
        }
    }
    __syncthreads();

    const float hsq = g_hsq[row];
    const int nc = min(scnt, MAXC);
    for (int ci = wid; ci < nc; ci += 8) {
        int c = scand[ci];
        const float* cp = cbp + (size_t)c * HID;
        float dot = 0.f;
#pragma unroll
        for (int k = lane; k < HID; k += 32) dot = fmaf(sh[k], cp[k], dot);
#pragma unroll
        for (int o = 16; o; o >>= 1) dot += __shfl_xor_sync(0xFFFFFFFFu, dot, o);
        if (lane == 0) {
            float s = __fadd_rn(__fsub_rn(hsq, __fmul_rn(2.0f, dot)), g_csq[c]);
            atomicMin(&skey, ((u64)enc_f(s) << 32) | (unsigned)c);
        }
    }
    __syncthreads();
    if (tid == 0) sidx = (unsigned)(skey & 0xFFFFFFFFull);
    __syncthreads();
    const unsigned idx = sidx;

    // --- Stream one-hot row: 2048 x 16B chunks (8192 floats), fused zeroing ---
    uint4* orow = (uint4*)(out + (size_t)row * NCODES);
    const int hot_chunk = idx >> 2;
    const int hot_sub = idx & 3;
    const unsigned h0 = (hot_sub == 0) ? 0x3F800000u : 0u;
    const unsigned h1 = (hot_sub == 1) ? 0x3F800000u : 0u;
    const unsigned h2 = (hot_sub == 2) ? 0x3F800000u : 0u;
    const unsigned h3 = (hot_sub == 3) ? 0x3F800000u : 0u;
#pragma unroll
    for (int it = 0; it < 8; ++it) {
        int c16 = it * 256 + tid;
        uint4 vv = make_uint4(0, 0, 0, 0);
        if (c16 == hot_chunk) { vv.x = h0; vv.y = h1; vv.z = h2; vv.w = h3; }
        orow[c16] = vv;
    }

    // --- Loss (warp 0): exact mean((h - z_q)^2) * 1.25 ---
    if (wid == 0) {
        const float* cp = cbp + (size_t)idx * HID;
        float s = 0.f;
#pragma unroll
        for (int k = lane; k < HID; k += 32) {
            float d = sh[k] - cp[k];
            s = fmaf(d, d, s);
        }
#pragma unroll
        for (int o = 16; o; o >>= 1) s += __shfl_xor_sync(0xFFFFFFFFu, s, o);
        if (lane == 0) {
            float m = s * (1.0f / (float)HID);
            out[(size_t)NROWS * NCODES + row] = __fadd_rn(m, __fmul_rn(0.25f, m));
        }
    }
}

// ---------------------------------------------------------------------------
extern "C" void kernel_launch(void* const* d_in, const int* in_sizes, int n_in,
                              void* d_out, int out_size) {
    const float* h  = (const float*)d_in[0];   // (8192, 256)
    const float* cb = (const float*)d_in[2];   // (8192, 256)
    float* out = (float*)d_out;

    static bool attr_set = false;
    if (!attr_set) {
        cudaFuncSetAttribute(vq_gemm_kernel,
                             cudaFuncAttributeMaxDynamicSharedMemorySize, SM_TOTAL);
        attr_set = true;
    }

    convert_norms_kernel<<<(NROWS + NCODES) / 8, 256>>>(h, cb);

    dim3 grid(NCODES / 128, NROWS / 128);  // (64, 64)
    vq_gemm_kernel<<<grid, 256, SM_TOTAL>>>();

    select_kernel<<<NROWS, 256>>>(h, cb, out);
}

// round 12
// speedup vs baseline: 2.2471x; 1.0645x over previous
#include <cuda_runtime.h>
#include <cuda_bf16.h>
#include <cstdint>

#define NROWS 8192
#define NCODES 8192
#define HID 256
#define EPS 1.0f
#define MAXC 256
#define NTILE 64                      // NCODES / 128

typedef unsigned long long u64;

// ---------------------------------------------------------------------------
// Device scratch (static globals — allocation-free)
// ---------------------------------------------------------------------------
__device__ __align__(16) __nv_bfloat16 g_hbf[NROWS * HID];
__device__ __align__(16) __nv_bfloat16 g_cbf[NCODES * HID];
__device__ float g_hsq[NROWS];
__device__ float g_csq[NCODES];
__device__ __align__(16) __nv_bfloat16 g_score[(size_t)NROWS * NCODES];  // 128 MB
__device__ float g_tmin[NTILE * NROWS];                                  // 2 MB, [tile][row]

__device__ __forceinline__ uint32_t smem_u32(const void* p) {
    uint32_t a;
    asm("{ .reg .u64 t; cvta.to.shared.u64 t, %1; cvt.u32.u64 %0, t; }"
        : "=r"(a) : "l"(p));
    return a;
}
__device__ __forceinline__ void cp16(uint32_t dst, const void* src) {
    asm volatile("cp.async.cg.shared.global [%0], [%1], 16;" :: "r"(dst), "l"(src));
}
#define CP_COMMIT() asm volatile("cp.async.commit_group;" ::: "memory")
#define CP_WAIT0()  asm volatile("cp.async.wait_group 0;"  ::: "memory")
#define CP_WAIT1()  asm volatile("cp.async.wait_group 1;"  ::: "memory")

#define LDSM_X4(r0, r1, r2, r3, addr)                                          \
    asm volatile("ldmatrix.sync.aligned.m8n8.x4.shared.b16 {%0,%1,%2,%3}, [%4];" \
                 : "=r"(r0), "=r"(r1), "=r"(r2), "=r"(r3) : "r"(addr))

#define MMA16816(d, a0, a1, a2, a3, b0, b1)                                    \
    asm volatile(                                                              \
        "mma.sync.aligned.m16n8k16.row.col.f32.bf16.bf16.f32 "                 \
        "{%0,%1,%2,%3}, {%4,%5,%6,%7}, {%8,%9}, {%0,%1,%2,%3};"                \
        : "+f"((d)[0]), "+f"((d)[1]), "+f"((d)[2]), "+f"((d)[3])               \
        : "r"(a0), "r"(a1), "r"(a2), "r"(a3), "r"(b0), "r"(b1))

// order-preserving float<->uint map
__device__ __forceinline__ unsigned enc_f(float f) {
    unsigned u = __float_as_uint(f);
    return (u & 0x80000000u) ? ~u : (u | 0x80000000u);
}
__device__ __forceinline__ float dec_f(unsigned e) {
    unsigned u = (e & 0x80000000u) ? (e ^ 0x80000000u) : ~e;
    return __uint_as_float(u);
}

// ---------------------------------------------------------------------------
// Fused fp32->bf16 convert + squared norms (one warp per row)
// ---------------------------------------------------------------------------
__global__ void convert_norms_kernel(const float* __restrict__ h,
                                     const float* __restrict__ cb) {
    int warp = (blockIdx.x * blockDim.x + threadIdx.x) >> 5;
    int lane = threadIdx.x & 31;
    const float* src;
    __nv_bfloat16* dst;
    float* nrm;
    if (warp < NROWS) {
        src = h + (size_t)warp * HID; dst = g_hbf + (size_t)warp * HID; nrm = &g_hsq[warp];
    } else {
        int r = warp - NROWS;
        if (r >= NCODES) return;
        src = cb + (size_t)r * HID; dst = g_cbf + (size_t)r * HID; nrm = &g_csq[r];
    }
    float s = 0.f;
#pragma unroll
    for (int half2i = 0; half2i < 2; ++half2i) {
        float4 a = ((const float4*)src)[lane + half2i * 32];
        s = fmaf(a.x, a.x, s); s = fmaf(a.y, a.y, s);
        s = fmaf(a.z, a.z, s); s = fmaf(a.w, a.w, s);
        __nv_bfloat162 p0 = __floats2bfloat162_rn(a.x, a.y);
        __nv_bfloat162 p1 = __floats2bfloat162_rn(a.z, a.w);
        uint2 w;
        w.x = *reinterpret_cast<uint32_t*>(&p0);
        w.y = *reinterpret_cast<uint32_t*>(&p1);
        ((uint2*)dst)[lane + half2i * 32] = w;
    }
#pragma unroll
    for (int o = 16; o; o >>= 1) s += __shfl_xor_sync(0xFFFFFFFFu, s, o);
    if (lane == 0) *nrm = s;
}

// ---------------------------------------------------------------------------
// bf16 HMMA GEMM: 128x128 tile per CTA (4096 CTAs), OCCUPANCY 2.
// K chunked 4x64, double-buffered cp.async.
// Epilogue: bf16 score staging -> coalesced writes + per-row tile-min index.
// ---------------------------------------------------------------------------
#define CH_STRIDE 144                    // 128B data + 16B pad, conflict-free
#define CH_MAT   (128 * CH_STRIDE)       // 18432 per matrix per chunk
#define CH_BUF   (2 * CH_MAT)            // A+B per chunk
#define SM_TOTAL (2 * CH_BUF)            // 73728 -> 2 CTAs/SM
#define SC_STRIDE 272                    // score staging row stride (bytes)
#define SM_ROWMIN 36864                  // rowmin array offset (after staging)

__global__ __launch_bounds__(256, 2) void vq_gemm_kernel() {
    extern __shared__ char smem[];
    const uint32_t sb = smem_u32(smem);
    const int tid = threadIdx.x;
    const int lane = tid & 31;
    const int wid = tid >> 5;
    const int wm = wid & 1;          // warp row (2 x 64)
    const int wn = wid >> 1;         // warp col (4 x 32)
    const int row0 = blockIdx.y * 128;
    const int col0 = blockIdx.x * 128;
    unsigned* rowmin = (unsigned*)(smem + SM_ROWMIN);

    const char* asrc = (const char*)(g_hbf + (size_t)row0 * HID);
    const char* bsrc = (const char*)(g_cbf + (size_t)col0 * HID);

    const int lr = tid >> 3;
    const int lc = tid & 7;
    auto load_chunk = [&](int ck, int buf) {
        const uint32_t bA = sb + buf * CH_BUF;
        const uint32_t bB = bA + CH_MAT;
        const int goff = ck * 128 + lc * 16;
#pragma unroll
        for (int i = 0; i < 4; ++i) {
            int r = lr + i * 32;
            cp16(bA + r * CH_STRIDE + lc * 16, asrc + r * 512 + goff);
            cp16(bB + r * CH_STRIDE + lc * 16, bsrc + r * 512 + goff);
        }
    };

    load_chunk(0, 0); CP_COMMIT();
    load_chunk(1, 1); CP_COMMIT();

    float acc[4][4][4];
#pragma unroll
    for (int mi = 0; mi < 4; ++mi)
#pragma unroll
        for (int ni = 0; ni < 4; ++ni)
#pragma unroll
            for (int q = 0; q < 4; ++q) acc[mi][ni][q] = 0.f;

    const int lrow = lane & 15;
    const int lkc  = lane >> 4;

#pragma unroll
    for (int ck = 0; ck < 4; ++ck) {
        if (ck < 3) CP_WAIT1(); else CP_WAIT0();
        __syncthreads();

        const uint32_t bufb = sb + (ck & 1) * CH_BUF;
        const uint32_t aAddr0 = bufb + (wm * 64 + lrow) * CH_STRIDE + lkc * 16;
        const uint32_t bAddr0 = bufb + CH_MAT + (wn * 32 + lrow) * CH_STRIDE + lkc * 16;
#pragma unroll
        for (int ks = 0; ks < 4; ++ks) {
            const uint32_t koff = (uint32_t)ks * 32;
            uint32_t a[4][4], b[2][4];
#pragma unroll
            for (int mi = 0; mi < 4; ++mi)
                LDSM_X4(a[mi][0], a[mi][1], a[mi][2], a[mi][3],
                        aAddr0 + mi * 16 * CH_STRIDE + koff);
#pragma unroll
            for (int nj = 0; nj < 2; ++nj)
                LDSM_X4(b[nj][0], b[nj][1], b[nj][2], b[nj][3],
                        bAddr0 + nj * 16 * CH_STRIDE + koff);
#pragma unroll
            for (int mi = 0; mi < 4; ++mi) {
#pragma unroll
                for (int nj = 0; nj < 2; ++nj) {
                    MMA16816(acc[mi][2 * nj],     a[mi][0], a[mi][1], a[mi][2], a[mi][3],
                             b[nj][0], b[nj][2]);
                    MMA16816(acc[mi][2 * nj + 1], a[mi][0], a[mi][1], a[mi][2], a[mi][3],
                             b[nj][1], b[nj][3]);
                }
            }
        }

        if (ck < 2) {
            __syncthreads();
            load_chunk(ck + 2, ck & 1);
            CP_COMMIT();
        }
    }
    __syncthreads();  // done with chunk buffers — reuse smem for staging/rowmin
    if (tid < 128) rowmin[tid] = 0xFFFFFFFFu;
    __syncthreads();

    // --- Epilogue: score = csq - 2*dot (in place) ---
    float2 csq2[4];
#pragma unroll
    for (int ni = 0; ni < 4; ++ni)
        csq2[ni] = *(const float2*)&g_csq[col0 + wn * 32 + ni * 8 + 2 * (lane & 3)];
#pragma unroll
    for (int mi = 0; mi < 4; ++mi)
#pragma unroll
        for (int ni = 0; ni < 4; ++ni) {
            acc[mi][ni][0] = csq2[ni].x - 2.0f * acc[mi][ni][0];
            acc[mi][ni][1] = csq2[ni].y - 2.0f * acc[mi][ni][1];
            acc[mi][ni][2] = csq2[ni].x - 2.0f * acc[mi][ni][2];
            acc[mi][ni][3] = csq2[ni].y - 2.0f * acc[mi][ni][3];
        }

    // per-row min across warp's 32 cols (quad shuffle) -> smem atomicMin
#pragma unroll
    for (int mi = 0; mi < 4; ++mi)
#pragma unroll
        for (int hh = 0; hh < 2; ++hh) {
            float m = acc[mi][0][2 * hh];
#pragma unroll
            for (int ni = 0; ni < 4; ++ni) {
                m = fminf(m, acc[mi][ni][2 * hh]);
                m = fminf(m, acc[mi][ni][2 * hh + 1]);
            }
            m = fminf(m, __shfl_xor_sync(0xFFFFFFFFu, m, 1));
            m = fminf(m, __shfl_xor_sync(0xFFFFFFFFu, m, 2));
            if ((lane & 3) == 0)
                atomicMin(&rowmin[wm * 64 + mi * 16 + (lane >> 2) + hh * 8], enc_f(m));
        }

    // --- stage bf16 scores in smem ---
    const int erow = wm * 64 + (lane >> 2);
    const int ecol = wn * 32 + 2 * (lane & 3);
#pragma unroll
    for (int mi = 0; mi < 4; ++mi) {
#pragma unroll
        for (int ni = 0; ni < 4; ++ni) {
            __nv_bfloat162 p01 = __floats2bfloat162_rn(acc[mi][ni][0], acc[mi][ni][1]);
            __nv_bfloat162 p23 = __floats2bfloat162_rn(acc[mi][ni][2], acc[mi][ni][3]);
            int r = erow + mi * 16;
            int cbyte = (ecol + ni * 8) * 2;
            *(uint32_t*)(smem + r * SC_STRIDE + cbyte) =
                *reinterpret_cast<uint32_t*>(&p01);
            *(uint32_t*)(smem + (r + 8) * SC_STRIDE + cbyte) =
                *reinterpret_cast<uint32_t*>(&p23);
        }
    }
    __syncthreads();

    // --- Coalesced copy-out: 128 rows x 256B + tile-min index ---
#pragma unroll
    for (int i = 0; i < 8; ++i) {
        int idx = tid + i * 256;
        int r = idx >> 4, q = idx & 15;
        uint4 v = *(const uint4*)(smem + r * SC_STRIDE + q * 16);
        *(uint4*)(g_score + (size_t)(row0 + r) * NCODES + col0 + q * 8) = v;
    }
    if (tid < 128)
        g_tmin[blockIdx.x * NROWS + row0 + tid] = dec_f(rowmin[tid]);
}

// ---------------------------------------------------------------------------
// Select + output: one block per row. Tile-min index -> qualifying tiles only
// -> candidates -> exact fp32 rescore -> one-hot stream (fused zeroing) + loss.
// ---------------------------------------------------------------------------
__global__ __launch_bounds__(256) void select_kernel(const float* __restrict__ h,
                                                     const float* __restrict__ cbp,
                                                     float* __restrict__ out) {
    const int row = blockIdx.x;
    const int tid = threadIdx.x;
    const int wid = tid >> 5;
    const int lane = tid & 31;
    const unsigned FULL = 0xFFFFFFFFu;

    __shared__ float sh[HID];
    __shared__ float stmin[NTILE];
    __shared__ float sthr;
    __shared__ int scand[MAXC];
    __shared__ int scnt;
    __shared__ unsigned long long skey;
    __shared__ unsigned sidx;

    if (tid == 0) { scnt = 0; skey = 0xFFFFFFFFFFFFFFFFull; }
    sh[tid] = h[(size_t)row * HID + tid];
    if (tid < NTILE) stmin[tid] = g_tmin[tid * NROWS + row];
    __syncthreads();

    if (wid == 0) {
        float m = fminf(stmin[lane], stmin[lane + 32]);
#pragma unroll
        for (int o = 16; o; o >>= 1) m = fminf(m, __shfl_xor_sync(FULL, m, o));
        if (lane == 0) sthr = m + EPS;
    }
    __syncthreads();
    const float thr = sthr;

    // scan only qualifying tiles (expected ~1-2)
    for (int t = wid; t < NTILE; t += 8) {
        if (stmin[t] < thr) {
            const __nv_bfloat162* sp =
                (const __nv_bfloat162*)(g_score + (size_t)row * NCODES + t * 128);
#pragma unroll
            for (int q = 0; q < 2; ++q) {
                float2 f = __bfloat1622float2(sp[lane * 2 + q]);
                if (f.x < thr) { int p = atomicAdd(&scnt, 1); if (p < MAXC) scand[p] = t * 128 + lane * 4 + q * 2; }
                if (f.y < thr) { int p = atomicAdd(&scnt, 1); if (p < MAXC) scand[p] = t * 128 + lane * 4 + q * 2 + 1; }
            }
        }
    }
    __syncthreads();

    const float hsq = g_hsq[row];
    const int nc = min(scnt, MAXC);
    for (int ci = wid; ci < nc; ci += 8) {
        int c = scand[ci];
        const float* cp = cbp + (size_t)c * HID;
        float dot = 0.f;
#pragma unroll
        for (int k = lane; k < HID; k += 32) dot = fmaf(sh[k], cp[k], dot);
#pragma unroll
        for (int o = 16; o; o >>= 1) dot += __shfl_xor_sync(FULL, dot, o);
        if (lane == 0) {
            float s = __fadd_rn(__fsub_rn(hsq, __fmul_rn(2.0f, dot)), g_csq[c]);
            atomicMin(&skey, ((u64)enc_f(s) << 32) | (unsigned)c);
        }
    }
    __syncthreads();
    if (tid == 0) sidx = (unsigned)(skey & 0xFFFFFFFFull);
    __syncthreads();
    const unsigned idx = sidx;

    // --- Stream one-hot row: 2048 x 16B chunks (8192 floats), fused zeroing ---
    uint4* orow = (uint4*)(out + (size_t)row * NCODES);
    const int hot_chunk = idx >> 2;
    const int hot_sub = idx & 3;
    const unsigned h0 = (hot_sub == 0) ? 0x3F800000u : 0u;
    const unsigned h1 = (hot_sub == 1) ? 0x3F800000u : 0u;
    const unsigned h2 = (hot_sub == 2) ? 0x3F800000u : 0u;
    const unsigned h3 = (hot_sub == 3) ? 0x3F800000u : 0u;
#pragma unroll
    for (int it = 0; it < 8; ++it) {
        int c16 = it * 256 + tid;
        uint4 vv = make_uint4(0, 0, 0, 0);
        if (c16 == hot_chunk) { vv.x = h0; vv.y = h1; vv.z = h2; vv.w = h3; }
        orow[c16] = vv;
    }

    // --- Loss (warp 0): exact mean((h - z_q)^2) * 1.25 ---
    if (wid == 0) {
        const float* cp = cbp + (size_t)idx * HID;
        float s = 0.f;
#pragma unroll
        for (int k = lane; k < HID; k += 32) {
            float d = sh[k] - cp[k];
            s = fmaf(d, d, s);
        }
#pragma unroll
        for (int o = 16; o; o >>= 1) s += __shfl_xor_sync(FULL, s, o);
        if (lane == 0) {
            float m = s * (1.0f / (float)HID);
            out[(size_t)NROWS * NCODES + row] = __fadd_rn(m, __fmul_rn(0.25f, m));
        }
    }
}

// ---------------------------------------------------------------------------
extern "C" void kernel_launch(void* const* d_in, const int* in_sizes, int n_in,
                              void* d_out, int out_size) {
    const float* h  = (const float*)d_in[0];   // (8192, 256)
    const float* cb = (const float*)d_in[2];   // (8192, 256)
    float* out = (float*)d_out;

    static bool attr_set = false;
    if (!attr_set) {
        cudaFuncSetAttribute(vq_gemm_kernel,
                             cudaFuncAttributeMaxDynamicSharedMemorySize, SM_TOTAL);
        attr_set = true;
    }

    convert_norms_kernel<<<(NROWS + NCODES) / 8, 256>>>(h, cb);

    dim3 grid(NCODES / 128, NROWS / 128);  // (64, 64)
    vq_gemm_kernel<<<grid, 256, SM_TOTAL>>>();

    select_kernel<<<NROWS, 256>>>(h, cb, out);
}